// round 11
// baseline (speedup 1.0000x reference)
#include <cuda_runtime.h>

// HopfieldNetwork: B=8, N=4096, ITERS=10 asynchronous sweeps.
// R11: speculative DUAL-FLIP rounds. Each barrier round commits flip A = g1
// (global min candidate, provably correct) and speculatively applies flip
// B = g2 (global 2nd). Validity is verified next round via a published
// violation min: candidates with key in (g1, g2] evaluated on z post-A
// (computed inside the fused loop BEFORE adding B's term). Valid <=> viol
// == g2. On misspeculation: rollback B (row kept in registers), commit the
// true flip v (or republish). Every committed flip is the position-min
// candidate at its point => flip sequence identical to serial reference.
// z int64 scale 2^40; wq = rn(W*2^40); flip delta = +-2*wq (IMAD.WIDE).

constexpr int NN  = 4096;
constexpr int TPB = 256;
constexpr int ZPT = 16;
constexpr int INF = 0x7FFFFFFF;

__device__ long long g_z[8 * NN];                      // z, int64, scale 2^40
__device__ __align__(16) int g_Wq[NN * NN];            // rn(W * 2^40)
__device__ __align__(16) unsigned char g_xsign[NN];    // bit b = (x[b][c] < 0)

// ---------------------------------------------------------------------------
__global__ void __launch_bounds__(256) prep_wq(const float* __restrict__ W,
                                               const float* __restrict__ x,
                                               int B)
{
    const int base = (blockIdx.x * 256 + threadIdx.x) * 16;
    const float4* w4 = reinterpret_cast<const float4*>(W + base);
    int4* o4 = reinterpret_cast<int4*>(g_Wq + base);
#pragma unroll
    for (int g = 0; g < 4; g++) {
        const float4 v = w4[g];
        int4 o;
        o.x = __float2int_rn(v.x * 0x1.0p40f);
        o.y = __float2int_rn(v.y * 0x1.0p40f);
        o.z = __float2int_rn(v.z * 0x1.0p40f);
        o.w = __float2int_rn(v.w * 0x1.0p40f);
        o4[g] = o;
    }
    if (blockIdx.x == 0) {
        for (int c = threadIdx.x * 16; c < threadIdx.x * 16 + 16; c++) {
            unsigned v = 0;
#pragma unroll
            for (int b = 0; b < 8; b++)
                if (b < B && x[(size_t)b * NN + c] < 0.f) v |= 1u << b;
            g_xsign[c] = (unsigned char)v;
        }
    }
}

// ---------------------------------------------------------------------------
__global__ void __launch_bounds__(256) gemv_init(int B)
{
    const int row  = blockIdx.x;
    const int tid  = threadIdx.x;
    const int base = tid * 16;
    const int lane = tid & 31, wid = tid >> 5;

    const uint4 sb4 = *reinterpret_cast<const uint4*>(g_xsign + base);
    const unsigned sb[4] = {sb4.x, sb4.y, sb4.z, sb4.w};

    const int4* w4 = reinterpret_cast<const int4*>(g_Wq + (size_t)row * NN + base);
    const int4 wa = w4[0], wb = w4[1], wc = w4[2], wd = w4[3];
    const int wq[16] = {wa.x, wa.y, wa.z, wa.w,  wb.x, wb.y, wb.z, wb.w,
                        wc.x, wc.y, wc.z, wc.w,  wd.x, wd.y, wd.z, wd.w};

    long long acc[8];
#pragma unroll
    for (int b = 0; b < 8; b++) acc[b] = 0ll;

#pragma unroll
    for (int k = 0; k < 16; k++) {
        const unsigned byte = (sb[k >> 2] >> (8 * (k & 3))) & 0xFFu;
        const int w = wq[k];
#pragma unroll
        for (int b = 0; b < 8; b++) {
            const int yb = 1 - 2 * (int)((byte >> b) & 1u);
            acc[b] += (long long)w * yb;
        }
    }

#pragma unroll
    for (int b = 0; b < 8; b++) {
#pragma unroll
        for (int off = 16; off > 0; off >>= 1)
            acc[b] += __shfl_down_sync(0xffffffffu, acc[b], off);
    }
    __shared__ long long red[8][8];
    if (lane == 0) {
#pragma unroll
        for (int b = 0; b < 8; b++) red[wid][b] = acc[b];
    }
    __syncthreads();
    if (tid < 8) {
        long long s = 0ll;
#pragma unroll
        for (int w2 = 0; w2 < 8; w2++) s += red[w2][tid];
        if (tid < B) g_z[tid * NN + row] = s;
    }
}

// ---------------------------------------------------------------------------
// Key pack: bits[0]=nb(=!y_sign), [1:13]=neuron i, [13:25]=pos-in-sweep.
// ---------------------------------------------------------------------------
__global__ void __launch_bounds__(TPB, 1) hopfield_seq(
    const float* __restrict__ x,
    const int*   __restrict__ perms,
    float*       __restrict__ out,
    int iters)
{
    const int b    = blockIdx.x;
    const int tid  = threadIdx.x;
    const int lane = tid & 31;
    const int wid  = tid >> 5;          // 8 warps
    const int base = tid * ZPT;

    __shared__ __align__(16) unsigned short pos_of[NN];
    __shared__ int sK1[2][8], sK2[2][8], sV[2][8];

    long long z[ZPT];
    {
        const long long* gz = g_z + (size_t)b * NN + base;
#pragma unroll
        for (int k = 0; k < ZPT; k++) z[k] = gz[k];
    }

    unsigned ym = 0;   // bit k = (y[base+k] < 0)
    {
        const float4* x4 = reinterpret_cast<const float4*>(x + (size_t)b * NN + base);
#pragma unroll
        for (int g = 0; g < 4; g++) {
            const float4 xv = x4[g];
            ym |= (__float_as_uint(xv.x) >> 31) << (4 * g + 0);
            ym |= (__float_as_uint(xv.y) >> 31) << (4 * g + 1);
            ym |= (__float_as_uint(xv.z) >> 31) << (4 * g + 2);
            ym |= (__float_as_uint(xv.w) >> 31) << (4 * g + 3);
        }
    }

    const int* pb = perms + (size_t)b * iters * NN;
    int parity  = 0;
    int specid1 = -1, specid2 = -1;
    int spec1[ZPT], spec2[ZPT], rbk[ZPT];
#pragma unroll
    for (int k = 0; k < ZPT; k++) { spec1[k] = 0; spec2[k] = 0; rbk[k] = 0; }

    // helper lambdas -------------------------------------------------------
    auto load_row = [&](int fi, int* dst) {
        const int4* w4 = reinterpret_cast<const int4*>(g_Wq + (size_t)fi * NN + base);
        const int4 da = __ldg(w4 + 0), db = __ldg(w4 + 1);
        const int4 dc = __ldg(w4 + 2), dd = __ldg(w4 + 3);
        dst[0]=da.x; dst[1]=da.y; dst[2]=da.z; dst[3]=da.w;
        dst[4]=db.x; dst[5]=db.y; dst[6]=db.z; dst[7]=db.w;
        dst[8]=dc.x; dst[9]=dc.y; dst[10]=dc.z; dst[11]=dc.w;
        dst[12]=dd.x; dst[13]=dd.y; dst[14]=dd.z; dst[15]=dd.w;
    };

    for (int sweep = 0; sweep < iters; sweep++) {
        // ---- neuron -> position table ----
        const int* ps = pb + sweep * NN;
        {
            const int4* p4 = reinterpret_cast<const int4*>(ps + tid * 16);
#pragma unroll
            for (int g = 0; g < 4; g++) {
                const int4 a = p4[g];
                const int p0 = tid * 16 + g * 4;
                pos_of[a.x] = (unsigned short)(p0 + 0);
                pos_of[a.y] = (unsigned short)(p0 + 1);
                pos_of[a.z] = (unsigned short)(p0 + 2);
                pos_of[a.w] = (unsigned short)(p0 + 3);
            }
        }
        __syncthreads();

        int ckey[ZPT], zmask[ZPT];
#pragma unroll
        for (int k = 0; k < ZPT; k++) {
            const int yb = (int)((ym >> k) & 1u);
            ckey[k]  = ((int)pos_of[base + k] << 13) | ((base + k) << 1) | (yb ^ 1);
            zmask[k] = yb << 31;
        }

        int pend = INF, thr_solid = -1;
        specid1 = specid2 = -1;

        // ---- initial publish (no flips this round) ----
        {
            unsigned m1 = INF;
#pragma unroll
            for (int k = 0; k < ZPT; k++) {
                const int t = (int)(z[k] >> 32) ^ zmask[k];
                if (t < 0) m1 = min(m1, (unsigned)ckey[k]);
            }
            const unsigned w1 = __reduce_min_sync(0xffffffffu, m1);
            const unsigned cb = (m1 == w1) ? (unsigned)INF : m1;
            const unsigned w2 = __reduce_min_sync(0xffffffffu, cb);
            if (lane == 0) { sK1[parity][wid] = (int)w1; sK2[parity][wid] = (int)w2;
                             sV[parity][wid] = INF; }
        }
        __syncthreads();

        for (;;) {
            const int a  = (lane < 8) ? sK1[parity][lane] : INF;
            const int bb = (lane < 8) ? sK2[parity][lane] : INF;
            const int c  = (lane < 8) ? sV[parity][lane]  : INF;
            parity ^= 1;
            const int g1 = (int)__reduce_min_sync(0xffffffffu, (unsigned)a);
            const int v  = (int)__reduce_min_sync(0xffffffffu, (unsigned)c);

            if (pend != INF) {
                if (v == pend) {                       // speculation valid
                    thr_solid = pend; pend = INF;
                } else {                               // misspeculation: rollback B
                    const int sfdB = 2 - 4 * (pend & 1);
                    const int fiB  = (pend >> 1) & 0xFFF;
#pragma unroll
                    for (int k = 0; k < ZPT; k++)
                        z[k] -= (long long)rbk[k] * sfdB;
                    if (tid == (fiB >> 4)) ym ^= 1u << (fiB & 15);
                    pend = INF; specid1 = specid2 = -1;

                    if (v != INF) {                    // v is the true next flip
                        const int fiv = (v >> 1) & 0xFFF;
                        const int sfd = 2 - 4 * (v & 1);
                        int dv[ZPT]; load_row(fiv, dv);
#pragma unroll
                        for (int k = 0; k < ZPT; k++)
                            z[k] += (long long)dv[k] * sfd;
                        if (tid == (fiv >> 4)) ym ^= 1u << (fiv & 15);
                        thr_solid = v;
                    }
                    // republish candidates > thr_solid on corrected z
                    unsigned m1 = INF;
#pragma unroll
                    for (int k = 0; k < ZPT; k++) {
                        const int t = (int)(z[k] >> 32) ^ zmask[k];
                        if (t < 0 && ckey[k] > thr_solid) m1 = min(m1, (unsigned)ckey[k]);
                    }
                    const unsigned w1 = __reduce_min_sync(0xffffffffu, m1);
                    const unsigned cb2 = (m1 == w1) ? (unsigned)INF : m1;
                    const unsigned w2 = __reduce_min_sync(0xffffffffu, cb2);
                    if (lane == 0) { sK1[parity][wid] = (int)w1; sK2[parity][wid] = (int)w2;
                                     sV[parity][wid] = INF; }
                    __syncthreads();
                    continue;
                }
            }

            if (g1 == INF) break;                      // sweep finished (validated)

            const int c2 = (a == g1) ? bb : a;
            const int g2 = (int)__reduce_min_sync(0xffffffffu, (unsigned)c2);

            // ---- flip A = g1 (committed) ----
            const int fiA  = (g1 >> 1) & 0xFFF;
            const int sfdA = 2 - 4 * (g1 & 1);
            int rowA[ZPT];
            if (fiA == specid1) {
#pragma unroll
                for (int k = 0; k < ZPT; k++) rowA[k] = spec1[k];
            } else if (fiA == specid2) {
#pragma unroll
                for (int k = 0; k < ZPT; k++) rowA[k] = spec2[k];
            } else {
                load_row(fiA, rowA);
            }
#pragma unroll
            for (int k = 0; k < ZPT; k++)
                z[k] += (long long)rowA[k] * sfdA;
            if (tid == (fiA >> 4)) ym ^= 1u << (fiA & 15);
            thr_solid = g1;

            unsigned m1 = INF, mv = INF;
            if (g2 != INF) {
                // ---- flip B = g2 (speculative) ----
                const int fiB  = (g2 >> 1) & 0xFFF;
                const int sfdB = 2 - 4 * (g2 & 1);
                if (fiB == specid1) {
#pragma unroll
                    for (int k = 0; k < ZPT; k++) rbk[k] = spec1[k];
                } else if (fiB == specid2) {
#pragma unroll
                    for (int k = 0; k < ZPT; k++) rbk[k] = spec2[k];
                } else {
                    load_row(fiB, rbk);
                }
                // fused: violation scan (post-A z) + axpy B + full candgen
#pragma unroll
                for (int k = 0; k < ZPT; k++) {
                    const int ck = ckey[k];
                    const int tA = (int)(z[k] >> 32) ^ zmask[k];
                    if (tA < 0 && ck > g1 && ck <= g2) mv = min(mv, (unsigned)ck);
                    z[k] += (long long)rbk[k] * sfdB;
                    const int tB = (int)(z[k] >> 32) ^ zmask[k];
                    if (tB < 0 && ck > g2) m1 = min(m1, (unsigned)ck);
                }
                if (tid == (fiB >> 4)) ym ^= 1u << (fiB & 15);
                pend = g2;
            } else {
#pragma unroll
                for (int k = 0; k < ZPT; k++) {
                    const int t = (int)(z[k] >> 32) ^ zmask[k];
                    if (t < 0 && ckey[k] > g1) m1 = min(m1, (unsigned)ckey[k]);
                }
                pend = INF;
            }

            // ---- spec rows for next round's predicted winners (g3, g4) ----
            {
                const int xx = (a == g1 || a == g2) ? INF : a;
                const int yy = (bb == g1 || bb == g2) ? INF : bb;
                const int g3 = (int)__reduce_min_sync(0xffffffffu,
                                                      (unsigned)min(xx, yy));
                const int xx2 = (xx == g3) ? INF : xx;
                const int yy2 = (yy == g3) ? INF : yy;
                const int g4 = (int)__reduce_min_sync(0xffffffffu,
                                                      (unsigned)min(xx2, yy2));
                specid1 = (g3 != INF) ? ((g3 >> 1) & 0xFFF) : -1;
                specid2 = (g4 != INF) ? ((g4 >> 1) & 0xFFF) : -1;
                if (specid1 >= 0) load_row(specid1, spec1);
                if (specid2 >= 0) load_row(specid2, spec2);
            }

            // ---- publish ----
            const unsigned w1 = __reduce_min_sync(0xffffffffu, m1);
            const unsigned cb3 = (m1 == w1) ? (unsigned)INF : m1;
            const unsigned w2 = __reduce_min_sync(0xffffffffu, cb3);
            const unsigned wv = __reduce_min_sync(0xffffffffu, mv);
            if (lane == 0) { sK1[parity][wid] = (int)w1; sK2[parity][wid] = (int)w2;
                             sV[parity][wid] = (int)wv; }
            __syncthreads();
        }
    }

    // ---- write y from register state ----
    float4* o4 = reinterpret_cast<float4*>(out + (size_t)b * NN + base);
#pragma unroll
    for (int g = 0; g < 4; g++) {
        float4 o;
        o.x = ((ym >> (4 * g + 0)) & 1u) ? -1.0f : 1.0f;
        o.y = ((ym >> (4 * g + 1)) & 1u) ? -1.0f : 1.0f;
        o.z = ((ym >> (4 * g + 2)) & 1u) ? -1.0f : 1.0f;
        o.w = ((ym >> (4 * g + 3)) & 1u) ? -1.0f : 1.0f;
        o4[g] = o;
    }
}

// ---------------------------------------------------------------------------
extern "C" void kernel_launch(void* const* d_in, const int* in_sizes, int n_in,
                              void* d_out, int out_size)
{
    const float* x     = (const float*)d_in[0];
    const float* W     = (const float*)d_in[1];
    const int*   perms = (const int*)  d_in[2];
    float*       out   = (float*)d_out;

    const int B     = in_sizes[0] / NN;
    const int iters = in_sizes[2] / in_sizes[0];

    prep_wq<<<NN * NN / (256 * 16), 256>>>(W, x, B);
    gemv_init<<<NN, 256>>>(B);
    hopfield_seq<<<B, TPB>>>(x, perms, out, iters);
}

// round 12
// speedup vs baseline: 1.0951x; 1.0951x over previous
#include <cuda_runtime.h>

// HopfieldNetwork: B=8, N=4096, ITERS=10 asynchronous sweeps.
// R12: LEAN dual-flip. Each round commits A=g1 (provably the next flip) and
// speculatively applies B=g2 (global 2nd candidate); validity is checked one
// round later via a published violation min over window (g1, g2] evaluated
// on post-A z (R11's protocol, proven rel_err=0). Cost fixes vs R11:
//  - ONE register spec row (g3 = predicted next-A); g4 only L1-prefetched.
//  - spec_id never invalidated (W rows are static data).
//  - register footprint trimmed (no spec2/dv arrays).
// z int64 scale 2^40; wq = rn(W*2^40); flip delta = +-2*wq via IMAD.WIDE.

constexpr int NN  = 4096;
constexpr int TPB = 256;
constexpr int ZPT = 16;
constexpr int INF = 0x7FFFFFFF;

__device__ long long g_z[8 * NN];                      // z, int64, scale 2^40
__device__ __align__(16) int g_Wq[NN * NN];            // rn(W * 2^40)
__device__ __align__(16) unsigned char g_xsign[NN];    // bit b = (x[b][c] < 0)

// ---------------------------------------------------------------------------
__global__ void __launch_bounds__(256) prep_wq(const float* __restrict__ W,
                                               const float* __restrict__ x,
                                               int B)
{
    const int base = (blockIdx.x * 256 + threadIdx.x) * 16;
    const float4* w4 = reinterpret_cast<const float4*>(W + base);
    int4* o4 = reinterpret_cast<int4*>(g_Wq + base);
#pragma unroll
    for (int g = 0; g < 4; g++) {
        const float4 v = w4[g];
        int4 o;
        o.x = __float2int_rn(v.x * 0x1.0p40f);
        o.y = __float2int_rn(v.y * 0x1.0p40f);
        o.z = __float2int_rn(v.z * 0x1.0p40f);
        o.w = __float2int_rn(v.w * 0x1.0p40f);
        o4[g] = o;
    }
    if (blockIdx.x == 0) {
        for (int c = threadIdx.x * 16; c < threadIdx.x * 16 + 16; c++) {
            unsigned v = 0;
#pragma unroll
            for (int b = 0; b < 8; b++)
                if (b < B && x[(size_t)b * NN + c] < 0.f) v |= 1u << b;
            g_xsign[c] = (unsigned char)v;
        }
    }
}

// ---------------------------------------------------------------------------
__global__ void __launch_bounds__(256) gemv_init(int B)
{
    const int row  = blockIdx.x;
    const int tid  = threadIdx.x;
    const int base = tid * 16;
    const int lane = tid & 31, wid = tid >> 5;

    const uint4 sb4 = *reinterpret_cast<const uint4*>(g_xsign + base);
    const unsigned sb[4] = {sb4.x, sb4.y, sb4.z, sb4.w};

    const int4* w4 = reinterpret_cast<const int4*>(g_Wq + (size_t)row * NN + base);
    const int4 wa = w4[0], wb = w4[1], wc = w4[2], wd = w4[3];
    const int wq[16] = {wa.x, wa.y, wa.z, wa.w,  wb.x, wb.y, wb.z, wb.w,
                        wc.x, wc.y, wc.z, wc.w,  wd.x, wd.y, wd.z, wd.w};

    long long acc[8];
#pragma unroll
    for (int b = 0; b < 8; b++) acc[b] = 0ll;

#pragma unroll
    for (int k = 0; k < 16; k++) {
        const unsigned byte = (sb[k >> 2] >> (8 * (k & 3))) & 0xFFu;
        const int w = wq[k];
#pragma unroll
        for (int b = 0; b < 8; b++) {
            const int yb = 1 - 2 * (int)((byte >> b) & 1u);
            acc[b] += (long long)w * yb;
        }
    }

#pragma unroll
    for (int b = 0; b < 8; b++) {
#pragma unroll
        for (int off = 16; off > 0; off >>= 1)
            acc[b] += __shfl_down_sync(0xffffffffu, acc[b], off);
    }
    __shared__ long long red[8][8];
    if (lane == 0) {
#pragma unroll
        for (int b = 0; b < 8; b++) red[wid][b] = acc[b];
    }
    __syncthreads();
    if (tid < 8) {
        long long s = 0ll;
#pragma unroll
        for (int w2 = 0; w2 < 8; w2++) s += red[w2][tid];
        if (tid < B) g_z[tid * NN + row] = s;
    }
}

// ---------------------------------------------------------------------------
// Key pack: bits[0]=nb(=!y_sign), [1:13]=neuron i, [13:25]=pos-in-sweep.
// ---------------------------------------------------------------------------
__global__ void __launch_bounds__(TPB, 1) hopfield_seq(
    const float* __restrict__ x,
    const int*   __restrict__ perms,
    float*       __restrict__ out,
    int iters)
{
    const int b    = blockIdx.x;
    const int tid  = threadIdx.x;
    const int lane = tid & 31;
    const int wid  = tid >> 5;          // 8 warps
    const int base = tid * ZPT;

    __shared__ __align__(16) unsigned short pos_of[NN];
    __shared__ int sK1[2][8], sK2[2][8], sV[2][8];

    long long z[ZPT];
    {
        const long long* gz = g_z + (size_t)b * NN + base;
#pragma unroll
        for (int k = 0; k < ZPT; k++) z[k] = gz[k];
    }

    unsigned ym = 0;   // bit k = (y[base+k] < 0)
    {
        const float4* x4 = reinterpret_cast<const float4*>(x + (size_t)b * NN + base);
#pragma unroll
        for (int g = 0; g < 4; g++) {
            const float4 xv = x4[g];
            ym |= (__float_as_uint(xv.x) >> 31) << (4 * g + 0);
            ym |= (__float_as_uint(xv.y) >> 31) << (4 * g + 1);
            ym |= (__float_as_uint(xv.z) >> 31) << (4 * g + 2);
            ym |= (__float_as_uint(xv.w) >> 31) << (4 * g + 3);
        }
    }

    const int* pb = perms + (size_t)b * iters * NN;
    int parity  = 0;
    int spec_id = -1;              // neuron whose Wq row sits in specv (static data)
    int specv[ZPT], rbk[ZPT];
#pragma unroll
    for (int k = 0; k < ZPT; k++) { specv[k] = 0; rbk[k] = 0; }

    auto load_row = [&](int fi, int* dst) {
        const int4* w4 = reinterpret_cast<const int4*>(g_Wq + (size_t)fi * NN + base);
        const int4 da = __ldg(w4 + 0), db = __ldg(w4 + 1);
        const int4 dc = __ldg(w4 + 2), dd = __ldg(w4 + 3);
        dst[0]=da.x;  dst[1]=da.y;  dst[2]=da.z;  dst[3]=da.w;
        dst[4]=db.x;  dst[5]=db.y;  dst[6]=db.z;  dst[7]=db.w;
        dst[8]=dc.x;  dst[9]=dc.y;  dst[10]=dc.z; dst[11]=dc.w;
        dst[12]=dd.x; dst[13]=dd.y; dst[14]=dd.z; dst[15]=dd.w;
    };

    for (int sweep = 0; sweep < iters; sweep++) {
        // ---- neuron -> position table ----
        const int* ps = pb + sweep * NN;
        {
            const int4* p4 = reinterpret_cast<const int4*>(ps + tid * 16);
#pragma unroll
            for (int g = 0; g < 4; g++) {
                const int4 a = p4[g];
                const int p0 = tid * 16 + g * 4;
                pos_of[a.x] = (unsigned short)(p0 + 0);
                pos_of[a.y] = (unsigned short)(p0 + 1);
                pos_of[a.z] = (unsigned short)(p0 + 2);
                pos_of[a.w] = (unsigned short)(p0 + 3);
            }
        }
        __syncthreads();

        int ckey[ZPT], zmask[ZPT];
#pragma unroll
        for (int k = 0; k < ZPT; k++) {
            const int yb = (int)((ym >> k) & 1u);
            ckey[k]  = ((int)pos_of[base + k] << 13) | ((base + k) << 1) | (yb ^ 1);
            zmask[k] = yb << 31;
        }

        int pend = INF, thr = -1;

        // ---- initial publish ----
        {
            unsigned m1 = INF;
#pragma unroll
            for (int k = 0; k < ZPT; k++) {
                const int t = (int)(z[k] >> 32) ^ zmask[k];
                if (t < 0) m1 = min(m1, (unsigned)ckey[k]);
            }
            const unsigned w1 = __reduce_min_sync(0xffffffffu, m1);
            const unsigned cb = (m1 == w1) ? (unsigned)INF : m1;
            const unsigned w2 = __reduce_min_sync(0xffffffffu, cb);
            if (lane == 0) { sK1[parity][wid] = (int)w1; sK2[parity][wid] = (int)w2;
                             sV[parity][wid] = INF; }
        }
        __syncthreads();

        for (;;) {
            const int a  = (lane < 8) ? sK1[parity][lane] : INF;
            const int bb = (lane < 8) ? sK2[parity][lane] : INF;
            const int c  = (lane < 8) ? sV[parity][lane]  : INF;
            parity ^= 1;
            const int g1 = (int)__reduce_min_sync(0xffffffffu, (unsigned)a);
            const int v  = (int)__reduce_min_sync(0xffffffffu, (unsigned)c);

            if (pend != INF) {
                if (v == pend) {                       // speculation valid
                    thr = pend; pend = INF;
                } else {                               // misspeculation: rollback B
                    const int sfdB = 2 - 4 * (pend & 1);
                    const int fiB  = (pend >> 1) & 0xFFF;
#pragma unroll
                    for (int k = 0; k < ZPT; k++)
                        z[k] -= (long long)rbk[k] * sfdB;
                    if (tid == (fiB >> 4)) ym ^= 1u << (fiB & 15);
                    pend = INF;

                    if (v != INF) {                    // v is the true next flip
                        const int fiv = (v >> 1) & 0xFFF;
                        const int sfd = 2 - 4 * (v & 1);
                        int rowv[ZPT];
                        if (fiv == spec_id) {
#pragma unroll
                            for (int k = 0; k < ZPT; k++) rowv[k] = specv[k];
                        } else {
                            load_row(fiv, rowv);
                        }
#pragma unroll
                        for (int k = 0; k < ZPT; k++)
                            z[k] += (long long)rowv[k] * sfd;
                        if (tid == (fiv >> 4)) ym ^= 1u << (fiv & 15);
                        thr = v;
                    }
                    // republish candidates > thr on corrected z
                    unsigned m1 = INF;
#pragma unroll
                    for (int k = 0; k < ZPT; k++) {
                        const int t = (int)(z[k] >> 32) ^ zmask[k];
                        if (t < 0 && ckey[k] > thr) m1 = min(m1, (unsigned)ckey[k]);
                    }
                    const unsigned w1 = __reduce_min_sync(0xffffffffu, m1);
                    const unsigned cb2 = (m1 == w1) ? (unsigned)INF : m1;
                    const unsigned w2 = __reduce_min_sync(0xffffffffu, cb2);
                    if (lane == 0) { sK1[parity][wid] = (int)w1; sK2[parity][wid] = (int)w2;
                                     sV[parity][wid] = INF; }
                    __syncthreads();
                    continue;
                }
            }

            if (g1 == INF) break;                      // sweep finished

            const int c2 = (a == g1) ? bb : a;
            const int g2 = (int)__reduce_min_sync(0xffffffffu, (unsigned)c2);

            // ---- flip A = g1 (committed) ----
            const int fiA  = (g1 >> 1) & 0xFFF;
            const int sfdA = 2 - 4 * (g1 & 1);
            {
                int rowA[ZPT];
                if (fiA == spec_id) {
#pragma unroll
                    for (int k = 0; k < ZPT; k++) rowA[k] = specv[k];
                } else {
                    load_row(fiA, rowA);
                }
#pragma unroll
                for (int k = 0; k < ZPT; k++)
                    z[k] += (long long)rowA[k] * sfdA;
            }
            if (tid == (fiA >> 4)) ym ^= 1u << (fiA & 15);
            thr = g1;

            unsigned m1 = INF, mv = INF;
            if (g2 != INF) {
                // ---- flip B = g2 (speculative) ----
                const int fiB  = (g2 >> 1) & 0xFFF;
                const int sfdB = 2 - 4 * (g2 & 1);
                if (fiB == spec_id) {
#pragma unroll
                    for (int k = 0; k < ZPT; k++) rbk[k] = specv[k];
                } else {
                    load_row(fiB, rbk);        // often L1-hit via last round's prefetch
                }
                // fused: violation scan (post-A z) + axpy B + candgen (post-B z)
#pragma unroll
                for (int k = 0; k < ZPT; k++) {
                    const int ck = ckey[k];
                    const int tA = (int)(z[k] >> 32) ^ zmask[k];
                    if (tA < 0 && ck > g1 && ck <= g2) mv = min(mv, (unsigned)ck);
                    z[k] += (long long)rbk[k] * sfdB;
                    const int tB = (int)(z[k] >> 32) ^ zmask[k];
                    if (tB < 0 && ck > g2) m1 = min(m1, (unsigned)ck);
                }
                if (tid == (fiB >> 4)) ym ^= 1u << (fiB & 15);
                pend = g2;
            } else {
#pragma unroll
                for (int k = 0; k < ZPT; k++) {
                    const int t = (int)(z[k] >> 32) ^ zmask[k];
                    if (t < 0 && ckey[k] > g1) m1 = min(m1, (unsigned)ckey[k]);
                }
                pend = INF;
            }

            // ---- spec hints: g3 -> register row, g4 -> L1 prefetch ----
            {
                const int xx = (a == g1 || a == g2) ? INF : a;
                const int yy = (bb == g1 || bb == g2) ? INF : bb;
                const int g3 = (int)__reduce_min_sync(0xffffffffu,
                                                      (unsigned)min(xx, yy));
                const int xx2 = (xx == g3) ? INF : xx;
                const int yy2 = (yy == g3) ? INF : yy;
                const int g4 = (int)__reduce_min_sync(0xffffffffu,
                                                      (unsigned)min(xx2, yy2));
                if (g3 != INF) {
                    spec_id = (g3 >> 1) & 0xFFF;
                    load_row(spec_id, specv);
                }
                if (g4 != INF) {
                    const char* p4 = reinterpret_cast<const char*>(
                        g_Wq + (size_t)((g4 >> 1) & 0xFFF) * NN + base);
                    asm volatile("prefetch.global.L1 [%0];" :: "l"(p4));
                }
            }

            // ---- publish ----
            const unsigned w1 = __reduce_min_sync(0xffffffffu, m1);
            const unsigned cb3 = (m1 == w1) ? (unsigned)INF : m1;
            const unsigned w2 = __reduce_min_sync(0xffffffffu, cb3);
            const unsigned wv = __reduce_min_sync(0xffffffffu, mv);
            if (lane == 0) { sK1[parity][wid] = (int)w1; sK2[parity][wid] = (int)w2;
                             sV[parity][wid] = (int)wv; }
            __syncthreads();
        }
    }

    // ---- write y from register state ----
    float4* o4 = reinterpret_cast<float4*>(out + (size_t)b * NN + base);
#pragma unroll
    for (int g = 0; g < 4; g++) {
        float4 o;
        o.x = ((ym >> (4 * g + 0)) & 1u) ? -1.0f : 1.0f;
        o.y = ((ym >> (4 * g + 1)) & 1u) ? -1.0f : 1.0f;
        o.z = ((ym >> (4 * g + 2)) & 1u) ? -1.0f : 1.0f;
        o.w = ((ym >> (4 * g + 3)) & 1u) ? -1.0f : 1.0f;
        o4[g] = o;
    }
}

// ---------------------------------------------------------------------------
extern "C" void kernel_launch(void* const* d_in, const int* in_sizes, int n_in,
                              void* d_out, int out_size)
{
    const float* x     = (const float*)d_in[0];
    const float* W     = (const float*)d_in[1];
    const int*   perms = (const int*)  d_in[2];
    float*       out   = (float*)d_out;

    const int B     = in_sizes[0] / NN;
    const int iters = in_sizes[2] / in_sizes[0];

    prep_wq<<<NN * NN / (256 * 16), 256>>>(W, x, B);
    gemv_init<<<NN, 256>>>(B);
    hopfield_seq<<<B, TPB>>>(x, perms, out, iters);
}

// round 13
// speedup vs baseline: 1.3336x; 1.2177x over previous
#include <cuda_runtime.h>

// HopfieldNetwork: B=8, N=4096, ITERS=10 asynchronous sweeps.
// R13 = R10 (best: 1387us) with TPB 256->512 (ZPT 16->8): same single-flip
// rounds, static per-sweep candidate keys, register spec row (2nd candidate)
// and L1 prefetch (3rd candidate) -- but 4 warps/SMSP instead of 2, so the
// LDS+REDUX decode chain and LDG latencies overlap other warps' issue.
// Dual-flip (R11/R12) measured worse; reverted.
// z int64 scale 2^40; wq = rn(W*2^40); flip delta = +-2*wq via IMAD.WIDE.

constexpr int NN  = 4096;
constexpr int TPB = 512;
constexpr int ZPT = 8;
constexpr int INF = 0x7FFFFFFF;

__device__ long long g_z[8 * NN];                      // z, int64, scale 2^40
__device__ __align__(16) int g_Wq[NN * NN];            // rn(W * 2^40)
__device__ __align__(16) unsigned char g_xsign[NN];    // bit b = (x[b][c] < 0)

// ---------------------------------------------------------------------------
__global__ void __launch_bounds__(256) prep_wq(const float* __restrict__ W,
                                               const float* __restrict__ x,
                                               int B)
{
    const int base = (blockIdx.x * 256 + threadIdx.x) * 16;
    const float4* w4 = reinterpret_cast<const float4*>(W + base);
    int4* o4 = reinterpret_cast<int4*>(g_Wq + base);
#pragma unroll
    for (int g = 0; g < 4; g++) {
        const float4 v = w4[g];
        int4 o;
        o.x = __float2int_rn(v.x * 0x1.0p40f);
        o.y = __float2int_rn(v.y * 0x1.0p40f);
        o.z = __float2int_rn(v.z * 0x1.0p40f);
        o.w = __float2int_rn(v.w * 0x1.0p40f);
        o4[g] = o;
    }
    if (blockIdx.x == 0) {
        for (int c = threadIdx.x * 16; c < threadIdx.x * 16 + 16; c++) {
            unsigned v = 0;
#pragma unroll
            for (int b = 0; b < 8; b++)
                if (b < B && x[(size_t)b * NN + c] < 0.f) v |= 1u << b;
            g_xsign[c] = (unsigned char)v;
        }
    }
}

// ---------------------------------------------------------------------------
__global__ void __launch_bounds__(256) gemv_init(int B)
{
    const int row  = blockIdx.x;
    const int tid  = threadIdx.x;
    const int base = tid * 16;
    const int lane = tid & 31, wid = tid >> 5;

    const uint4 sb4 = *reinterpret_cast<const uint4*>(g_xsign + base);
    const unsigned sb[4] = {sb4.x, sb4.y, sb4.z, sb4.w};

    const int4* w4 = reinterpret_cast<const int4*>(g_Wq + (size_t)row * NN + base);
    const int4 wa = w4[0], wb = w4[1], wc = w4[2], wd = w4[3];
    const int wq[16] = {wa.x, wa.y, wa.z, wa.w,  wb.x, wb.y, wb.z, wb.w,
                        wc.x, wc.y, wc.z, wc.w,  wd.x, wd.y, wd.z, wd.w};

    long long acc[8];
#pragma unroll
    for (int b = 0; b < 8; b++) acc[b] = 0ll;

#pragma unroll
    for (int k = 0; k < 16; k++) {
        const unsigned byte = (sb[k >> 2] >> (8 * (k & 3))) & 0xFFu;
        const int w = wq[k];
#pragma unroll
        for (int b = 0; b < 8; b++) {
            const int yb = 1 - 2 * (int)((byte >> b) & 1u);
            acc[b] += (long long)w * yb;          // IMAD.WIDE
        }
    }

#pragma unroll
    for (int b = 0; b < 8; b++) {
#pragma unroll
        for (int off = 16; off > 0; off >>= 1)
            acc[b] += __shfl_down_sync(0xffffffffu, acc[b], off);
    }
    __shared__ long long red[8][8];
    if (lane == 0) {
#pragma unroll
        for (int b = 0; b < 8; b++) red[wid][b] = acc[b];
    }
    __syncthreads();
    if (tid < 8) {
        long long s = 0ll;
#pragma unroll
        for (int w2 = 0; w2 < 8; w2++) s += red[w2][tid];
        if (tid < B) g_z[tid * NN + row] = s;
    }
}

// ---------------------------------------------------------------------------
// Kernel 2: one block per sample, one barrier per flip.
// Key pack: bits[0]=nb(=!y_sign), [1:13]=neuron i, [13:25]=pos-in-sweep.
// ---------------------------------------------------------------------------
__global__ void __launch_bounds__(TPB, 1) hopfield_seq(
    const float* __restrict__ x,
    const int*   __restrict__ perms,
    float*       __restrict__ out,
    int iters)
{
    const int b    = blockIdx.x;
    const int tid  = threadIdx.x;
    const int lane = tid & 31;
    const int wid  = tid >> 5;          // 16 warps
    const int base = tid * ZPT;

    __shared__ __align__(16) unsigned short pos_of[NN];   // neuron -> pos
    __shared__ __align__(16) int sh_slot[2][16];

    // ---- load z slice and x signs into registers ----
    long long z[ZPT];
    {
        const long long* gz = g_z + (size_t)b * NN + base;
#pragma unroll
        for (int k = 0; k < ZPT; k++) z[k] = gz[k];
    }

    unsigned ym = 0;   // bit k = (y[base+k] < 0)
    {
        const float4* x4 = reinterpret_cast<const float4*>(x + (size_t)b * NN + base);
#pragma unroll
        for (int g = 0; g < 2; g++) {
            const float4 xv = x4[g];
            ym |= (__float_as_uint(xv.x) >> 31) << (4 * g + 0);
            ym |= (__float_as_uint(xv.y) >> 31) << (4 * g + 1);
            ym |= (__float_as_uint(xv.z) >> 31) << (4 * g + 2);
            ym |= (__float_as_uint(xv.w) >> 31) << (4 * g + 3);
        }
    }

    const int* pb = perms + (size_t)b * iters * NN;
    int parity  = 0;
    int spec_id = -1;          // neuron whose Wq row sits in specv
    int specv[ZPT];
#pragma unroll
    for (int k = 0; k < ZPT; k++) specv[k] = 0;

    for (int sweep = 0; sweep < iters; sweep++) {
        // ---- build neuron -> position table for this sweep ----
        const int* ps = pb + sweep * NN;
        {
            const int4* p4 = reinterpret_cast<const int4*>(ps + tid * 8);
#pragma unroll
            for (int g = 0; g < 2; g++) {
                const int4 a = p4[g];
                const int p0 = tid * 8 + g * 4;
                pos_of[a.x] = (unsigned short)(p0 + 0);
                pos_of[a.y] = (unsigned short)(p0 + 1);
                pos_of[a.z] = (unsigned short)(p0 + 2);
                pos_of[a.w] = (unsigned short)(p0 + 3);
            }
        }
        __syncthreads();                         // pos_of visible

        // ---- static per-sweep candidate keys + sign-xor masks ----
        int ckey[ZPT];      // (pos<<13)|(neuron<<1)|(!y_sign)
        int zmask[ZPT];     // y_sign << 31
#pragma unroll
        for (int k = 0; k < ZPT; k++) {
            const int yb = (int)((ym >> k) & 1u);
            ckey[k]  = ((int)pos_of[base + k] << 13) | ((base + k) << 1) | (yb ^ 1);
            zmask[k] = yb << 31;
        }

        int thr = -1;

        // ---- initial candidates for this sweep ----
        {
            unsigned key = (unsigned)INF;
#pragma unroll
            for (int k = 0; k < ZPT; k++) {
                const int t = (int)(z[k] >> 32) ^ zmask[k];
                if (t < 0) key = min(key, (unsigned)ckey[k]);
            }
            const unsigned wmin = __reduce_min_sync(0xffffffffu, key);
            if (lane == 0) sh_slot[parity][wid] = (int)wmin;
        }
        __syncthreads();                         // slots visible

        // ---- flip rounds: one barrier each ----
        for (;;) {
            // lane-parallel decode: one slot per lane, redux for top-3
            const int a  = (lane < 16) ? sh_slot[parity][lane] : INF;
            parity ^= 1;
            const int mk = (int)__reduce_min_sync(0xffffffffu, (unsigned)a);
            if (mk == INF) break;                // sweep finished

            const int e  = (a == mk) ? INF : a;
            const int r2 = (int)__reduce_min_sync(0xffffffffu, (unsigned)e);

            const int fi = (mk >> 1) & 0xFFF;
            const int nb = mk & 1;
            thr = mk;

            // flip delta is +-2*W at scale 2^40 -> add +-2*wq
            const int sfd = 2 - 4 * nb;

            // ---- axpy: one IMAD.WIDE per element ----
            if (fi == spec_id) {                 // uniform branch: spec hit
#pragma unroll
                for (int k = 0; k < ZPT; k++)
                    z[k] += (long long)specv[k] * sfd;
            } else {                             // miss: demand load
                const int4* w4 =
                    reinterpret_cast<const int4*>(g_Wq + (size_t)fi * NN + base);
                const int4 da = __ldg(w4 + 0), db = __ldg(w4 + 1);
                const int dv[ZPT] = {da.x, da.y, da.z, da.w,
                                     db.x, db.y, db.z, db.w};
#pragma unroll
                for (int k = 0; k < ZPT; k++)
                    z[k] += (long long)dv[k] * sfd;
            }

            // ---- speculative register load of 2nd candidate's row ----
            const int nsid = (r2 != INF) ? ((r2 >> 1) & 0xFFF) : -1;
            if (nsid >= 0) {                     // uniform branch
                const int4* s4 =
                    reinterpret_cast<const int4*>(g_Wq + (size_t)nsid * NN + base);
                const int4 sa = __ldg(s4 + 0), sb_ = __ldg(s4 + 1);
                specv[0] = sa.x;  specv[1] = sa.y;  specv[2] = sa.z;  specv[3] = sa.w;
                specv[4] = sb_.x; specv[5] = sb_.y; specv[6] = sb_.z; specv[7] = sb_.w;
            }
            spec_id = nsid;

            // ---- L1 prefetch of 3rd candidate's row (off critical path) ----
            {
                const int e3 = (a == mk || a == r2) ? INF : a;
                const int r3 = (int)__reduce_min_sync(0xffffffffu, (unsigned)e3);
                if (r3 != INF) {
                    const char* p3 = reinterpret_cast<const char*>(
                        g_Wq + (size_t)((r3 >> 1) & 0xFFF) * NN + base);
                    asm volatile("prefetch.global.L1 [%0];" :: "l"(p3));
                }
            }

            // owner records the flip in its y bits (stale ckey/zmask excluded
            // by ckey > thr for the rest of the sweep)
            if (tid == (fi >> 3)) ym ^= 1u << (fi & 7);

            // ---- candidate regeneration: static keys, sign-xor test ----
            {
                unsigned key = (unsigned)INF;
#pragma unroll
                for (int k = 0; k < ZPT; k++) {
                    const int t = (int)(z[k] >> 32) ^ zmask[k];
                    if (t < 0 && ckey[k] > thr) key = min(key, (unsigned)ckey[k]);
                }
                const unsigned wmin = __reduce_min_sync(0xffffffffu, key);
                if (lane == 0) sh_slot[parity][wid] = (int)wmin;
            }
            __syncthreads();                     // the single barrier
        }
    }

    // ---- write y from register state ----
    float4* o4 = reinterpret_cast<float4*>(out + (size_t)b * NN + base);
#pragma unroll
    for (int g = 0; g < 2; g++) {
        float4 o;
        o.x = ((ym >> (4 * g + 0)) & 1u) ? -1.0f : 1.0f;
        o.y = ((ym >> (4 * g + 1)) & 1u) ? -1.0f : 1.0f;
        o.z = ((ym >> (4 * g + 2)) & 1u) ? -1.0f : 1.0f;
        o.w = ((ym >> (4 * g + 3)) & 1u) ? -1.0f : 1.0f;
        o4[g] = o;
    }
}

// ---------------------------------------------------------------------------
extern "C" void kernel_launch(void* const* d_in, const int* in_sizes, int n_in,
                              void* d_out, int out_size)
{
    const float* x     = (const float*)d_in[0];
    const float* W     = (const float*)d_in[1];
    const int*   perms = (const int*)  d_in[2];
    float*       out   = (float*)d_out;

    const int B     = in_sizes[0] / NN;
    const int iters = in_sizes[2] / in_sizes[0];

    prep_wq<<<NN * NN / (256 * 16), 256>>>(W, x, B);
    gemv_init<<<NN, 256>>>(B);
    hopfield_seq<<<B, TPB>>>(x, perms, out, iters);
}